// round 3
// baseline (speedup 1.0000x reference)
#include <cuda_runtime.h>
#include <cstdint>

typedef unsigned long long ull;

#define BB 512
#define TT 1024
#define IDIM 15
#define HH 64
#define ODIM 11
#define CHUNK 32
#define NCHUNK (TT/CHUNK)

// scratch (static __device__ — no allocations in kernel_launch)
__device__ __align__(16) float g_xpad[(size_t)BB*TT*16];   // x padded 15 -> 16
__device__ __align__(16) float g_hs[(size_t)BB*TT*HH];     // all hidden states

// ---- f32x2 helpers ----
__device__ __forceinline__ ull ffma2(ull a, ull b, ull c){
    ull d; asm("fma.rn.f32x2 %0, %1, %2, %3;" : "=l"(d) : "l"(a), "l"(b), "l"(c)); return d;
}
__device__ __forceinline__ ull fadd2(ull a, ull b){
    ull d; asm("add.rn.f32x2 %0, %1, %2;" : "=l"(d) : "l"(a), "l"(b)); return d;
}
__device__ __forceinline__ ull pack2(float x, float y){
    ull r; asm("mov.b64 %0, {%1, %2};" : "=l"(r) : "f"(x), "f"(y)); return r;
}
__device__ __forceinline__ float2 unpack2(ull v){
    float2 r; asm("mov.b64 {%0, %1}, %2;" : "=f"(r.x), "=f"(r.y) : "l"(v)); return r;
}

// ---- kernel 0: pad x [B,T,15] -> [B,T,16], float4 both directions via smem ----
__global__ void __launch_bounds__(256) pad_x_kernel(const float* __restrict__ x){
    __shared__ float xsm[256*IDIM];          // 256 rows x 15 floats = 15KB
    const int tid = threadIdx.x;
    // load 960 float4 (3840 floats) coalesced
    const float4* src4 = (const float4*)(x + (size_t)blockIdx.x * (256*IDIM));
    #pragma unroll
    for (int k=0;k<4;k++){
        int idx = tid + k*256;
        if (idx < 960) ((float4*)xsm)[idx] = src4[idx];
    }
    __syncthreads();
    // store 1024 float4 (256 rows x 16 floats) coalesced
    float4* dst4 = (float4*)(g_xpad + (size_t)blockIdx.x * (256*16));
    #pragma unroll
    for (int k=0;k<4;k++){
        int idx = tid + k*256;
        int row = idx >> 2, q = idx & 3;
        const float* rp = xsm + row*IDIM + q*4;
        float f0 = rp[0], f1 = rp[1], f2 = rp[2];
        float f3 = (q == 3) ? 0.f : rp[3];
        dst4[idx] = make_float4(f0, f1, f2, f3);
    }
}

// ---- kernel 1: recurrence, 2 warps per batch (32 outputs each), 4 batches/block ----
__global__ void __launch_bounds__(256,1) rnn_kernel(
    const float* __restrict__ W_ih, const float* __restrict__ b_ih,
    const float* __restrict__ W_hh, const float* __restrict__ b_hh,
    float* __restrict__ h_out)
{
    __shared__ __align__(16) float xs[2][4][CHUNK*16];   // x chunks: 2 x 4 x 2KB = 16KB
    __shared__ __align__(16) float h_sh[4][2][HH];       // per-batch double-buffered h

    const int tid  = threadIdx.x;
    const int wid  = tid >> 5;          // 0..7
    const int l    = tid & 31;
    const int p    = wid >> 1;          // batch pair slot 0..3
    const int half = wid & 1;           // which 32 outputs
    const int b    = blockIdx.x * 4 + p;
    const int j    = half*32 + l;       // this lane's output index

    // W_hh row j in registers, k-paired as f32x2 (32 ull = 64 regs)
    ull w[32];
    {
        const ull* wp = (const ull*)W_hh;
        #pragma unroll
        for (int q=0;q<32;q++) w[q] = wp[j*32 + q];
    }
    // W_ih row j, i-paired (i=15 padded with 0)
    ull wi[8];
    #pragma unroll
    for (int q=0;q<8;q++){
        float a0 = W_ih[j*IDIM + 2*q];
        float a1 = (2*q+1 < IDIM) ? W_ih[j*IDIM + 2*q + 1] : 0.f;
        wi[q] = pack2(a0, a1);
    }
    const float bias = b_ih[j] + b_hh[j];

    // h_{-1} = 0 lives in buf 1 (t=0 reads buf 1)
    h_sh[p][1][j] = 0.f;

    const uint32_t xs_base = (uint32_t)__cvta_generic_to_shared(&xs[0][p][0]);
    const float* xsrc = g_xpad + (size_t)b * (TT*16);

    // each warp fetches its half of the batch-chunk (64 x 16B)
    auto prefetch = [&](int c){
        if (c < NCHUNK){
            const float* src = xsrc + (size_t)c * (CHUNK*16);
            uint32_t dst = xs_base + (uint32_t)(c & 1) * (uint32_t)sizeof(xs[0]);
            #pragma unroll
            for (int q=0;q<2;q++){
                int idx = half*64 + q*32 + l;   // 0..127 16B units
                asm volatile("cp.async.ca.shared.global [%0], [%1], 16;\n"
                    :: "r"(dst + (uint32_t)(idx*16)), "l"(src + idx*4) : "memory");
            }
        }
        asm volatile("cp.async.commit_group;\n" ::: "memory");
    };

    prefetch(0);
    __syncthreads();   // h init + barrier baseline

    const int bar_id = 1 + p;   // named barrier per batch (64 threads)
    float* hs_g = g_hs + (size_t)b * (TT*HH) + j;
    float hlast = 0.f;

    for (int c=0; c<NCHUNK; c++){
        prefetch(c+1);
        asm volatile("cp.async.wait_group 1;\n" ::: "memory");  // own half of chunk c landed
        asm volatile("bar.sync %0, 64;\n" :: "r"(bar_id) : "memory");  // partner half too
        const float* xpb = &xs[c & 1][p][0];

        #pragma unroll 4
        for (int tt=0; tt<CHUNK; tt++){
            const int rs = (tt & 1) ^ 1;
            const int ws =  tt & 1;

            // input projection: 16 floats broadcast, 8 ffma2
            const ulonglong2* xv = (const ulonglong2*)(xpb + tt*16);
            ull xa = pack2(bias, 0.f);
            #pragma unroll
            for (int q=0;q<4;q++){
                ulonglong2 xq = xv[q];
                xa = ffma2(xq.x, wi[2*q],   xa);
                xa = ffma2(xq.y, wi[2*q+1], xa);
            }

            // recurrence: full h_{t-1} broadcast, 32 ffma2, 2 chains
            const ulonglong2* hp = (const ulonglong2*)&h_sh[p][rs][0];
            ull a0 = 0ULL, a1 = 0ULL;
            #pragma unroll
            for (int q=0;q<16;q++){
                ulonglong2 hv = hp[q];
                a0 = ffma2(hv.x, w[2*q],   a0);
                a1 = ffma2(hv.y, w[2*q+1], a1);
            }
            float2 s  = unpack2(fadd2(fadd2(a0, a1), xa));
            float hv  = fmaxf(s.x + s.y, 0.f);

            h_sh[p][ws][j] = hv;                 // exchange (STS.32)
            hs_g[(size_t)(c*CHUNK + tt)*HH] = hv; // coalesced 128B STG.32 per half-warp
            hlast = hv;
            asm volatile("bar.sync %0, 64;\n" :: "r"(bar_id) : "memory");
        }
    }
    // final hidden state -> tail of d_out ( [1,B,H] )
    h_out[b*HH + j] = hlast;
}

// ---- kernel 2: decoder out = relu(hs @ W_dec^T + b_dec) ----
__global__ void __launch_bounds__(128) dec_kernel(
    const float* __restrict__ W_dec, const float* __restrict__ b_dec,
    float* __restrict__ out)
{
    __shared__ __align__(16) float wd_f[ODIM*HH];
    __shared__ float bd[ODIM];
    __shared__ __align__(16) ull  rows[4][32*33];
    __shared__ __align__(16) float outsh[4][32*ODIM];

    for (int i = threadIdx.x; i < ODIM*HH; i += 128) wd_f[i] = W_dec[i];
    if (threadIdx.x < ODIM) bd[threadIdx.x] = b_dec[threadIdx.x];
    __syncthreads();

    const int wid = threadIdx.x >> 5;
    const int l   = threadIdx.x & 31;
    const int ngroups = (BB*TT)/32;

    for (int g = blockIdx.x*4 + wid; g < ngroups; g += gridDim.x*4){
        const ulonglong2* src = (const ulonglong2*)(g_hs + (size_t)g * (32*64));
        #pragma unroll
        for (int q=0;q<16;q++){
            int idx = q*32 + l;
            ulonglong2 v = src[idx];
            int row = idx >> 4;
            int cu  = (idx & 15) * 2;
            rows[wid][row*33 + cu]     = v.x;
            rows[wid][row*33 + cu + 1] = v.y;
        }
        __syncwarp();
        const ull* hr  = &rows[wid][l*33];
        const ull* wd2 = (const ull*)wd_f;
        #pragma unroll
        for (int o=0;o<ODIM;o++){
            ull a0=0ULL, a1=0ULL;
            #pragma unroll
            for (int kk=0;kk<32;kk+=2){
                a0 = ffma2(hr[kk],   wd2[o*32+kk],   a0);
                a1 = ffma2(hr[kk+1], wd2[o*32+kk+1], a1);
            }
            float2 s = unpack2(fadd2(a0,a1));
            outsh[wid][l*ODIM + o] = fmaxf(s.x + s.y + bd[o], 0.f);
        }
        __syncwarp();
        float4* dst = (float4*)(out + (size_t)g * (32*ODIM));
        const float4* osrc = (const float4*)&outsh[wid][0];
        #pragma unroll
        for (int q=0;q<3;q++){
            int idx = q*32 + l;
            if (idx < 88) dst[idx] = osrc[idx];
        }
        __syncwarp();
    }
}

extern "C" void kernel_launch(void* const* d_in, const int* in_sizes, int n_in,
                              void* d_out, int out_size)
{
    const float* x     = (const float*)d_in[0];
    const float* W_ih  = (const float*)d_in[1];
    const float* b_ih  = (const float*)d_in[2];
    const float* W_hh  = (const float*)d_in[3];
    const float* b_hh  = (const float*)d_in[4];
    const float* W_dec = (const float*)d_in[5];
    const float* b_dec = (const float*)d_in[6];
    float* out = (float*)d_out;

    (void)in_sizes; (void)n_in; (void)out_size;

    pad_x_kernel<<<(BB*TT)/256, 256>>>(x);
    rnn_kernel<<<BB/4, 256>>>(W_ih, b_ih, W_hh, b_hh, out + (size_t)BB*TT*ODIM);
    dec_kernel<<<1024, 128>>>(W_dec, b_dec, out);
}